// round 12
// baseline (speedup 1.0000x reference)
#include <cuda_runtime.h>
#include <cuda_bf16.h>
#include <math.h>
#include <stdint.h>

#define S_LEN 2048
#define HID   2048
#define NH    16
#define HD    128
#define QKV_N 6144
#define EPS   1e-5f
#define QSCALE 0.08838834764831845f

__device__ __nv_bfloat16 g_lnx_hi [S_LEN * HID];
__device__ __nv_bfloat16 g_lnx_lo [S_LEN * HID];
__device__ __nv_bfloat16 g_wqkv_hi[QKV_N * HID];
__device__ __nv_bfloat16 g_wqkv_lo[QKV_N * HID];
__device__ __nv_bfloat16 g_wproj_hi[HID * HID];
__device__ __nv_bfloat16 g_wproj_lo[HID * HID];
__device__ __nv_bfloat16 g_q_hi[S_LEN * HID];
__device__ __nv_bfloat16 g_q_lo[S_LEN * HID];
__device__ __nv_bfloat16 g_k_hi[S_LEN * HID];
__device__ __nv_bfloat16 g_k_lo[S_LEN * HID];
__device__ __nv_bfloat16 g_v_hi[S_LEN * HID];
__device__ __nv_bfloat16 g_v_lo[S_LEN * HID];
__device__ __nv_bfloat16 g_ctx_hi[S_LEN * HID];
__device__ __nv_bfloat16 g_ctx_lo[S_LEN * HID];

__device__ __forceinline__ uint32_t smem_u32(const void* p) {
    uint32_t a;
    asm("{ .reg .u64 t; cvta.to.shared.u64 t, %1; cvt.u32.u64 %0, t; }" : "=r"(a) : "l"(p));
    return a;
}
__device__ __forceinline__ void ldm_x4(uint32_t* r, uint32_t addr) {
    asm volatile("ldmatrix.sync.aligned.m8n8.x4.shared.b16 {%0,%1,%2,%3}, [%4];"
        : "=r"(r[0]), "=r"(r[1]), "=r"(r[2]), "=r"(r[3]) : "r"(addr));
}
__device__ __forceinline__ void ldm_x4t(uint32_t* r, uint32_t addr) {
    asm volatile("ldmatrix.sync.aligned.m8n8.x4.trans.shared.b16 {%0,%1,%2,%3}, [%4];"
        : "=r"(r[0]), "=r"(r[1]), "=r"(r[2]), "=r"(r[3]) : "r"(addr));
}
__device__ __forceinline__ void mma_bf16(float* d, const uint32_t* a, uint32_t b0, uint32_t b1) {
    asm volatile("mma.sync.aligned.m16n8k16.row.col.f32.bf16.bf16.f32 "
        "{%0,%1,%2,%3}, {%4,%5,%6,%7}, {%8,%9}, {%0,%1,%2,%3};"
        : "+f"(d[0]), "+f"(d[1]), "+f"(d[2]), "+f"(d[3])
        : "r"(a[0]), "r"(a[1]), "r"(a[2]), "r"(a[3]), "r"(b0), "r"(b1));
}
__device__ __forceinline__ void cp16(uint32_t saddr, const void* g) {
    asm volatile("cp.async.cg.shared.global [%0], [%1], 16;" :: "r"(saddr), "l"(g));
}
#define CP_COMMIT() asm volatile("cp.async.commit_group;" ::: "memory")
#define CP_WAIT1()  asm volatile("cp.async.wait_group 1;" ::: "memory")
#define CP_WAIT0()  asm volatile("cp.async.wait_group 0;" ::: "memory")

__device__ __forceinline__ void split_pack(float a, float b, uint32_t& hi, uint32_t& lo) {
    __nv_bfloat162 h = __floats2bfloat162_rn(a, b);
    hi = *(uint32_t*)&h;
    __nv_bfloat162 l = __floats2bfloat162_rn(a - __bfloat162float(h.x),
                                             b - __bfloat162float(h.y));
    lo = *(uint32_t*)&l;
}
__device__ __forceinline__ void split4_store(float4 v, __nv_bfloat16* hp, __nv_bfloat16* lp) {
    uint32_t h0, l0, h1, l1;
    split_pack(v.x, v.y, h0, l0);
    split_pack(v.z, v.w, h1, l1);
    *(uint2*)hp = make_uint2(h0, h1);
    *(uint2*)lp = make_uint2(l0, l1);
}

// ---------------- LayerNorm ----------------
__global__ __launch_bounds__(256)
void layernorm_kernel(const float* __restrict__ x, const float* __restrict__ w,
                      const float* __restrict__ b) {
    int s = blockIdx.x, tid = threadIdx.x;
    const float* row = x + (size_t)s * HID;
    float4 a = *(const float4*)(row + tid * 4);
    float4 c = *(const float4*)(row + 1024 + tid * 4);
    float s1 = a.x + a.y + a.z + a.w + c.x + c.y + c.z + c.w;
    float s2 = a.x*a.x + a.y*a.y + a.z*a.z + a.w*a.w
             + c.x*c.x + c.y*c.y + c.z*c.z + c.w*c.w;
    #pragma unroll
    for (int off = 16; off; off >>= 1) {
        s1 += __shfl_xor_sync(0xffffffffu, s1, off);
        s2 += __shfl_xor_sync(0xffffffffu, s2, off);
    }
    __shared__ float r1[8], r2[8];
    int wrp = tid >> 5, lane = tid & 31;
    if (lane == 0) { r1[wrp] = s1; r2[wrp] = s2; }
    __syncthreads();
    if (tid == 0) {
        float t1 = 0.f, t2 = 0.f;
        #pragma unroll
        for (int i = 0; i < 8; i++) { t1 += r1[i]; t2 += r2[i]; }
        r1[0] = t1; r2[0] = t2;
    }
    __syncthreads();
    float mu = r1[0] * (1.f / HID);
    float var = r2[0] * (1.f / HID) - mu * mu;
    float rs = rsqrtf(var + EPS);
    size_t rbase = (size_t)s * HID;
    int c0 = tid * 4;
    float4 w0 = *(const float4*)(w + c0), b0 = *(const float4*)(b + c0);
    float4 o0 = make_float4((a.x-mu)*rs*w0.x+b0.x, (a.y-mu)*rs*w0.y+b0.y,
                            (a.z-mu)*rs*w0.z+b0.z, (a.w-mu)*rs*w0.w+b0.w);
    split4_store(o0, g_lnx_hi + rbase + c0, g_lnx_lo + rbase + c0);
    int c1 = 1024 + tid * 4;
    float4 w1 = *(const float4*)(w + c1), b1 = *(const float4*)(b + c1);
    float4 o1 = make_float4((c.x-mu)*rs*w1.x+b1.x, (c.y-mu)*rs*w1.y+b1.y,
                            (c.z-mu)*rs*w1.z+b1.z, (c.w-mu)*rs*w1.w+b1.w);
    split4_store(o1, g_lnx_hi + rbase + c1, g_lnx_lo + rbase + c1);
}

__global__ __launch_bounds__(256)
void splitw_kernel(const float* __restrict__ x, int which, int n) {
    __nv_bfloat16* hi = which ? g_wproj_hi : g_wqkv_hi;
    __nv_bfloat16* lo = which ? g_wproj_lo : g_wqkv_lo;
    int i = (blockIdx.x * 256 + threadIdx.x) * 4;
    if (i < n) split4_store(*(const float4*)(x + i), hi + i, lo + i);
}

// ---- GEMM: 512 threads, 128x256 CTA tile, 3-stage cp.async pipeline ----
#define BK 32
#define A_HI_OFF 0
#define A_LO_OFF 8192
#define B_HI_OFF 16384
#define B_LO_OFF 32768
#define STAGE_BYTES 49152
#define GSMEM (3 * STAGE_BYTES)

template<int WHICH>
__global__ __launch_bounds__(512, 1)
void gemm_tmpl(const float* __restrict__ bias, float* __restrict__ Cout, int ldc) {
    extern __shared__ __align__(1024) char smem[];
    const __nv_bfloat16 *Ahi, *Alo, *Bhi, *Blo;
    if (WHICH == 0) { Ahi = g_lnx_hi; Alo = g_lnx_lo; Bhi = g_wqkv_hi; Blo = g_wqkv_lo; }
    else            { Ahi = g_ctx_hi; Alo = g_ctx_lo; Bhi = g_wproj_hi; Blo = g_wproj_lo; }
    const int NCHUNK = HID / BK;
    uint32_t sb = smem_u32(smem);
    int tid = threadIdx.x, wid = tid >> 5, lane = tid & 31;
    int row0 = blockIdx.y * 128, col0 = blockIdx.x * 256;
    int wm = wid >> 3, wn = wid & 7;

    int soffA; size_t gaA;
    {
        int r = tid >> 2, c16 = tid & 3, tr = r & 15;
        soffA = ((r >> 4) * 2 + (c16 >> 1)) * 512 + tr * 32
              + (((c16 & 1) ^ ((tr >> 2) & 1))) * 16;
        gaA = (size_t)(row0 + r) * HID + c16 * 8;
    }
    int soffB[2]; size_t gbB[2];
    #pragma unroll
    for (int j = 0; j < 2; j++) {
        int v = tid + j * 512;
        int r = v >> 2, c16 = v & 3, tr = r & 15;
        soffB[j] = ((r >> 4) * 2 + (c16 >> 1)) * 512 + tr * 32
                 + (((c16 & 1) ^ ((tr >> 2) & 1))) * 16;
        gbB[j] = (size_t)(col0 + r) * HID + c16 * 8;
    }
    float acc[4][4][4];
    #pragma unroll
    for (int i = 0; i < 4; i++)
        #pragma unroll
        for (int j = 0; j < 4; j++)
            #pragma unroll
            for (int q = 0; q < 4; q++) acc[i][j][q] = 0.f;
    int lr = lane & 15, lch = lane >> 4;
    int laneoff = lr * 32 + ((lch ^ ((lr >> 2) & 1))) * 16;

    #pragma unroll
    for (int c = 0; c < 2; c++) {
        uint32_t base = sb + c * STAGE_BYTES;
        int k0 = c * BK;
        cp16(base + A_HI_OFF + soffA, Ahi + gaA + k0);
        cp16(base + A_LO_OFF + soffA, Alo + gaA + k0);
        #pragma unroll
        for (int j = 0; j < 2; j++) {
            cp16(base + B_HI_OFF + soffB[j], Bhi + gbB[j] + k0);
            cp16(base + B_LO_OFF + soffB[j], Blo + gbB[j] + k0);
        }
        CP_COMMIT();
    }

    int buf = 0, bpre = 2;
    for (int c = 0; c < NCHUNK; c++) {
        if (c == NCHUNK - 1) CP_WAIT0(); else CP_WAIT1();
        __syncthreads();
        if (c + 2 < NCHUNK) {
            uint32_t base = sb + bpre * STAGE_BYTES;
            int k0 = (c + 2) * BK;
            cp16(base + A_HI_OFF + soffA, Ahi + gaA + k0);
            cp16(base + A_LO_OFF + soffA, Alo + gaA + k0);
            #pragma unroll
            for (int j = 0; j < 2; j++) {
                cp16(base + B_HI_OFF + soffB[j], Bhi + gbB[j] + k0);
                cp16(base + B_LO_OFF + soffB[j], Blo + gbB[j] + k0);
            }
            CP_COMMIT();
        }
        uint32_t stg = sb + buf * STAGE_BYTES;
        #pragma unroll
        for (int kt = 0; kt < 2; kt++) {
            uint32_t aT0 = stg + ((wm * 4) * 2 + kt) * 512 + laneoff;
            uint32_t bT0 = stg + ((wn * 2) * 2 + kt) * 512 + laneoff;
            uint32_t bH[2][4], bL[2][4];
            #pragma unroll
            for (int j = 0; j < 2; j++) ldm_x4(bH[j], bT0 + B_HI_OFF + j * 1024);
            #pragma unroll
            for (int j = 0; j < 2; j++) ldm_x4(bL[j], bT0 + B_LO_OFF + j * 1024);
            #pragma unroll
            for (int mt = 0; mt < 4; mt++) {
                uint32_t aH[4], aL[4];
                ldm_x4(aH, aT0 + A_HI_OFF + mt * 1024);
                #pragma unroll
                for (int j = 0; j < 2; j++) {
                    mma_bf16(acc[mt][j*2+0], aH, bH[j][0], bH[j][2]);
                    mma_bf16(acc[mt][j*2+1], aH, bH[j][1], bH[j][3]);
                }
                ldm_x4(aL, aT0 + A_LO_OFF + mt * 1024);
                #pragma unroll
                for (int j = 0; j < 2; j++) {
                    mma_bf16(acc[mt][j*2+0], aH, bL[j][0], bL[j][2]);
                    mma_bf16(acc[mt][j*2+1], aH, bL[j][1], bL[j][3]);
                }
                #pragma unroll
                for (int j = 0; j < 2; j++) {
                    mma_bf16(acc[mt][j*2+0], aL, bH[j][0], bH[j][2]);
                    mma_bf16(acc[mt][j*2+1], aL, bH[j][1], bH[j][3]);
                }
            }
        }
        buf = (buf == 2) ? 0 : buf + 1;
        bpre = (bpre == 2) ? 0 : bpre + 1;
    }

    int rg = lane >> 2, cg = (lane & 3) * 2;
    #pragma unroll
    for (int mt = 0; mt < 4; mt++) {
        int row = row0 + wm * 64 + mt * 16 + rg;
        #pragma unroll
        for (int n8 = 0; n8 < 4; n8++) {
            int col = col0 + wn * 32 + n8 * 8 + cg;
            float b0 = bias[col], b1 = bias[col + 1];
            if (WHICH == 0) {
                int seg = col >> 11, cs = col & 2047;
                float sc = (seg == 0) ? QSCALE : 1.f;
                __nv_bfloat16 *hp = (seg == 0) ? g_q_hi : (seg == 1) ? g_k_hi : g_v_hi;
                __nv_bfloat16 *lp = (seg == 0) ? g_q_lo : (seg == 1) ? g_k_lo : g_v_lo;
                uint32_t hi, lo;
                split_pack((acc[mt][n8][0]+b0)*sc, (acc[mt][n8][1]+b1)*sc, hi, lo);
                *(uint32_t*)(hp + (size_t)row * HID + cs) = hi;
                *(uint32_t*)(lp + (size_t)row * HID + cs) = lo;
                split_pack((acc[mt][n8][2]+b0)*sc, (acc[mt][n8][3]+b1)*sc, hi, lo);
                *(uint32_t*)(hp + (size_t)(row + 8) * HID + cs) = hi;
                *(uint32_t*)(lp + (size_t)(row + 8) * HID + cs) = lo;
            } else {
                *(float2*)(Cout + (size_t)row * ldc + col) =
                    make_float2(acc[mt][n8][0]+b0, acc[mt][n8][1]+b1);
                *(float2*)(Cout + (size_t)(row + 8) * ldc + col) =
                    make_float2(acc[mt][n8][2]+b0, acc[mt][n8][3]+b1);
            }
        }
    }
}

// ---------------- FA2 attention, mma.sync bf16x3 (unchanged) ----------------
#define QH_OFF 0
#define QL_OFF 32768
#define ST_OFF 65536
#define ST_STRIDE 65536
#define AKH 0
#define AKL 16384
#define AVH 32768
#define AVL 49152
#define ASMEM (ST_OFF + 2 * ST_STRIDE)

__global__ __launch_bounds__(256, 1)
void attn_mma_kernel() {
    extern __shared__ __align__(1024) char smem[];
    uint32_t sb = smem_u32(smem);
    int tid = threadIdx.x, wid = tid >> 5, lane = tid & 31, l15 = lane & 15;
    int h = blockIdx.y;
    int qb = (int)gridDim.x - 1 - (int)blockIdx.x;
    int q0 = qb * 128;
    int ntiles = qb * 2 + 2;
    size_t hoff = (size_t)h * HD;

    int qs[8]; size_t qg[8];
    #pragma unroll
    for (int j = 0; j < 8; j++) {
        int v = tid + j * 256;
        int r = v >> 4, c16 = v & 15, tc = c16 >> 1;
        qs[j] = ((r >> 4) * 8 + tc) * 512 + (((r & 15) ^ tc) * 32)
              + (((c16 & 1) ^ ((r >> 2) & 1)) * 16);
        qg[j] = (size_t)(q0 + r) * HID + hoff + c16 * 8;
    }
    int ks[4]; size_t kg[4];
    #pragma unroll
    for (int j = 0; j < 4; j++) {
        int v = tid + j * 256;
        int r = v >> 4, c16 = v & 15, tc = c16 >> 1;
        ks[j] = ((r >> 4) * 8 + tc) * 512 + (((r & 15) ^ tc) * 32)
              + (((c16 & 1) ^ ((r >> 2) & 1)) * 16);
        kg[j] = (size_t)r * HID + hoff + c16 * 8;
    }

    #pragma unroll
    for (int j = 0; j < 8; j++) {
        cp16(sb + QH_OFF + qs[j], g_q_hi + qg[j]);
        cp16(sb + QL_OFF + qs[j], g_q_lo + qg[j]);
    }
    CP_COMMIT();
    #pragma unroll
    for (int t = 0; t < 2; t++) {
        uint32_t stb = sb + ST_OFF + t * ST_STRIDE;
        size_t kvb = (size_t)(t * 64) * HID;
        #pragma unroll
        for (int j = 0; j < 4; j++) {
            cp16(stb + AKH + ks[j], g_k_hi + kvb + kg[j]);
            cp16(stb + AKL + ks[j], g_k_lo + kvb + kg[j]);
            cp16(stb + AVH + ks[j], g_v_hi + kvb + kg[j]);
            cp16(stb + AVL + ks[j], g_v_lo + kvb + kg[j]);
        }
        CP_COMMIT();
    }

    int slotoff = ((lane >> 4) ^ ((lane >> 2) & 1)) * 16;
    int gr = q0 + wid * 16 + (lane >> 2);
    int colb = 2 * (lane & 3);

    float o[16][4];
    #pragma unroll
    for (int i = 0; i < 16; i++)
        #pragma unroll
        for (int j = 0; j < 4; j++) o[i][j] = 0.f;
    float m0 = -INFINITY, m1 = -INFINITY, l0 = 0.f, l1 = 0.f;

    for (int t = 0; t < ntiles; t++) {
        if (t >= ntiles - 2) CP_WAIT0(); else CP_WAIT1();
        __syncthreads();
        uint32_t stb = sb + ST_OFF + (t & 1) * ST_STRIDE;
        int kt0 = t * 64;
        bool active = (q0 + wid * 16 + 15) >= kt0;

        if (active) {
            float s[8][4];
            #pragma unroll
            for (int i = 0; i < 8; i++)
                #pragma unroll
                for (int j = 0; j < 4; j++) s[i][j] = 0.f;

            #pragma unroll
            for (int kc = 0; kc < 8; kc++) {
                int tl = ((l15 ^ kc) * 32) + slotoff;
                uint32_t qh[4], ql[4], kh[4][4], kl[4][4];
                ldm_x4(qh, sb + QH_OFF + (wid * 8 + kc) * 512 + tl);
                ldm_x4(ql, sb + QL_OFF + (wid * 8 + kc) * 512 + tl);
                #pragma unroll
                for (int ng = 0; ng < 4; ng++) ldm_x4(kh[ng], stb + AKH + (ng * 8 + kc) * 512 + tl);
                #pragma unroll
                for (int ng = 0; ng < 4; ng++) ldm_x4(kl[ng], stb + AKL + (ng * 8 + kc) * 512 + tl);
                #pragma unroll
                for (int ng = 0; ng < 4; ng++) {
                    mma_bf16(s[2*ng],   qh, kh[ng][0], kh[ng][2]);
                    mma_bf16(s[2*ng+1], qh, kh[ng][1], kh[ng][3]);
                    mma_bf16(s[2*ng],   qh, kl[ng][0], kl[ng][2]);
                    mma_bf16(s[2*ng+1], qh, kl[ng][1], kl[ng][3]);
                    mma_bf16(s[2*ng],   ql, kh[ng][0], kh[ng][2]);
                    mma_bf16(s[2*ng+1], ql, kh[ng][1], kh[ng][3]);
                }
            }

            if (kt0 + 63 > gr) {
                #pragma unroll
                for (int t8 = 0; t8 < 8; t8++) {
                    int col = kt0 + t8 * 8 + colb;
                    if (col > gr)         s[t8][0] = -INFINITY;
                    if (col + 1 > gr)     s[t8][1] = -INFINITY;
                    if (col > gr + 8)     s[t8][2] = -INFINITY;
                    if (col + 1 > gr + 8) s[t8][3] = -INFINITY;
                }
            }

            float tm0 = m0, tm1 = m1;
            #pragma unroll
            for (int t8 = 0; t8 < 8; t8++) {
                tm0 = fmaxf(tm0, fmaxf(s[t8][0], s[t8][1]));
                tm1 = fmaxf(tm1, fmaxf(s[t8][2], s[t8][3]));
            }
            tm0 = fmaxf(tm0, __shfl_xor_sync(0xffffffffu, tm0, 1));
            tm0 = fmaxf(tm0, __shfl_xor_sync(0xffffffffu, tm0, 2));
            tm1 = fmaxf(tm1, __shfl_xor_sync(0xffffffffu, tm1, 1));
            tm1 = fmaxf(tm1, __shfl_xor_sync(0xffffffffu, tm1, 2));
            float c0 = __expf(m0 - tm0), c1 = __expf(m1 - tm1);
            m0 = tm0; m1 = tm1;
            float rs0 = 0.f, rs1 = 0.f;
            #pragma unroll
            for (int t8 = 0; t8 < 8; t8++) {
                s[t8][0] = __expf(s[t8][0] - m0); rs0 += s[t8][0];
                s[t8][1] = __expf(s[t8][1] - m0); rs0 += s[t8][1];
                s[t8][2] = __expf(s[t8][2] - m1); rs1 += s[t8][2];
                s[t8][3] = __expf(s[t8][3] - m1); rs1 += s[t8][3];
            }
            rs0 += __shfl_xor_sync(0xffffffffu, rs0, 1);
            rs0 += __shfl_xor_sync(0xffffffffu, rs0, 2);
            rs1 += __shfl_xor_sync(0xffffffffu, rs1, 1);
            rs1 += __shfl_xor_sync(0xffffffffu, rs1, 2);
            l0 = l0 * c0 + rs0;
            l1 = l1 * c1 + rs1;
            #pragma unroll
            for (int i = 0; i < 16; i++) {
                o[i][0] *= c0; o[i][1] *= c0; o[i][2] *= c1; o[i][3] *= c1;
            }

            #pragma unroll
            for (int kc2 = 0; kc2 < 4; kc2++) {
                uint32_t ph[4], pl[4];
                split_pack(s[2*kc2][0],   s[2*kc2][1],   ph[0], pl[0]);
                split_pack(s[2*kc2][2],   s[2*kc2][3],   ph[1], pl[1]);
                split_pack(s[2*kc2+1][0], s[2*kc2+1][1], ph[2], pl[2]);
                split_pack(s[2*kc2+1][2], s[2*kc2+1][3], ph[3], pl[3]);
                #pragma unroll
                for (int dd = 0; dd < 8; dd++) {
                    int tl = ((l15 ^ dd) * 32) + slotoff;
                    uint32_t vh[4], vl[4];
                    ldm_x4t(vh, stb + AVH + (kc2 * 8 + dd) * 512 + tl);
                    ldm_x4t(vl, stb + AVL + (kc2 * 8 + dd) * 512 + tl);
                    mma_bf16(o[dd*2],   ph, vh[0], vh[1]);
                    mma_bf16(o[dd*2+1], ph, vh[2], vh[3]);
                    mma_bf16(o[dd*2],   ph, vl[0], vl[1]);
                    mma_bf16(o[dd*2+1], ph, vl[2], vl[3]);
                    mma_bf16(o[dd*2],   pl, vh[0], vh[1]);
                    mma_bf16(o[dd*2+1], pl, vh[2], vh[3]);
                }
            }
        }
        __syncthreads();
        if (t + 2 < ntiles) {
            uint32_t stb2 = sb + ST_OFF + (t & 1) * ST_STRIDE;
            size_t kvb = (size_t)((t + 2) * 64) * HID;
            #pragma unroll
            for (int j = 0; j < 4; j++) {
                cp16(stb2 + AKH + ks[j], g_k_hi + kvb + kg[j]);
                cp16(stb2 + AKL + ks[j], g_k_lo + kvb + kg[j]);
                cp16(stb2 + AVH + ks[j], g_v_hi + kvb + kg[j]);
                cp16(stb2 + AVL + ks[j], g_v_lo + kvb + kg[j]);
            }
            CP_COMMIT();
        }
    }

    float inv0 = 1.f / l0, inv1 = 1.f / l1;
    size_t ob0 = (size_t)gr * HID + hoff + colb;
    size_t ob1 = (size_t)(gr + 8) * HID + hoff + colb;
    #pragma unroll
    for (int n8 = 0; n8 < 16; n8++) {
        uint32_t hi, lo;
        split_pack(o[n8][0] * inv0, o[n8][1] * inv0, hi, lo);
        *(uint32_t*)(g_ctx_hi + ob0 + n8 * 8) = hi;
        *(uint32_t*)(g_ctx_lo + ob0 + n8 * 8) = lo;
        split_pack(o[n8][2] * inv1, o[n8][3] * inv1, hi, lo);
        *(uint32_t*)(g_ctx_hi + ob1 + n8 * 8) = hi;
        *(uint32_t*)(g_ctx_lo + ob1 + n8 * 8) = lo;
    }
}

extern "C" void kernel_launch(void* const* d_in, const int* in_sizes, int n_in,
                              void* d_out, int out_size) {
    const float* hs   = (const float*)d_in[0];
    const float* lw   = (const float*)d_in[1];
    const float* lb   = (const float*)d_in[2];
    const float* qkvw = (const float*)d_in[3];
    const float* qkvb = (const float*)d_in[4];
    const float* pw   = (const float*)d_in[5];
    const float* pb   = (const float*)d_in[6];
    float* out = (float*)d_out;

    cudaFuncSetAttribute(gemm_tmpl<0>, cudaFuncAttributeMaxDynamicSharedMemorySize, GSMEM);
    cudaFuncSetAttribute(gemm_tmpl<1>, cudaFuncAttributeMaxDynamicSharedMemorySize, GSMEM);
    cudaFuncSetAttribute(attn_mma_kernel, cudaFuncAttributeMaxDynamicSharedMemorySize, ASMEM);

    layernorm_kernel<<<S_LEN, 256>>>(hs, lw, lb);
    splitw_kernel<<<(QKV_N * HID / 4) / 256, 256>>>(qkvw, 0, QKV_N * HID);
    splitw_kernel<<<(HID * HID / 4) / 256, 256>>>(pw, 1, HID * HID);
    gemm_tmpl<0><<<dim3(QKV_N / 256, S_LEN / 128), 512, GSMEM>>>(qkvb, nullptr, QKV_N);
    attn_mma_kernel<<<dim3(S_LEN / 128, NH), 256, ASMEM>>>();
    gemm_tmpl<1><<<dim3(HID / 256, S_LEN / 128), 512, GSMEM>>>(pb, out, HID);
}

// round 15
// speedup vs baseline: 1.0154x; 1.0154x over previous
#include <cuda_runtime.h>
#include <cuda_bf16.h>
#include <math.h>
#include <stdint.h>

#define S_LEN 2048
#define HID   2048
#define NH    16
#define HD    128
#define QKV_N 6144
#define EPS   1e-5f
#define QSCALE 0.08838834764831845f

__device__ __nv_bfloat16 g_lnx_hi [S_LEN * HID];
__device__ __nv_bfloat16 g_lnx_lo [S_LEN * HID];
__device__ __nv_bfloat16 g_wqkv_hi[QKV_N * HID];
__device__ __nv_bfloat16 g_wqkv_lo[QKV_N * HID];
__device__ __nv_bfloat16 g_wproj_hi[HID * HID];
__device__ __nv_bfloat16 g_wproj_lo[HID * HID];
__device__ __nv_bfloat16 g_q_hi[S_LEN * HID];
__device__ __nv_bfloat16 g_q_lo[S_LEN * HID];
__device__ __nv_bfloat16 g_k_hi[S_LEN * HID];
__device__ __nv_bfloat16 g_k_lo[S_LEN * HID];
__device__ __nv_bfloat16 g_v_hi[S_LEN * HID];
__device__ __nv_bfloat16 g_v_lo[S_LEN * HID];
__device__ __nv_bfloat16 g_ctx_hi[S_LEN * HID];
__device__ __nv_bfloat16 g_ctx_lo[S_LEN * HID];

__device__ __forceinline__ uint32_t smem_u32(const void* p) {
    uint32_t a;
    asm("{ .reg .u64 t; cvta.to.shared.u64 t, %1; cvt.u32.u64 %0, t; }" : "=r"(a) : "l"(p));
    return a;
}
__device__ __forceinline__ void ldm_x4(uint32_t* r, uint32_t addr) {
    asm volatile("ldmatrix.sync.aligned.m8n8.x4.shared.b16 {%0,%1,%2,%3}, [%4];"
        : "=r"(r[0]), "=r"(r[1]), "=r"(r[2]), "=r"(r[3]) : "r"(addr));
}
__device__ __forceinline__ void ldm_x4t(uint32_t* r, uint32_t addr) {
    asm volatile("ldmatrix.sync.aligned.m8n8.x4.trans.shared.b16 {%0,%1,%2,%3}, [%4];"
        : "=r"(r[0]), "=r"(r[1]), "=r"(r[2]), "=r"(r[3]) : "r"(addr));
}
__device__ __forceinline__ void mma_bf16(float* d, const uint32_t* a, uint32_t b0, uint32_t b1) {
    asm volatile("mma.sync.aligned.m16n8k16.row.col.f32.bf16.bf16.f32 "
        "{%0,%1,%2,%3}, {%4,%5,%6,%7}, {%8,%9}, {%0,%1,%2,%3};"
        : "+f"(d[0]), "+f"(d[1]), "+f"(d[2]), "+f"(d[3])
        : "r"(a[0]), "r"(a[1]), "r"(a[2]), "r"(a[3]), "r"(b0), "r"(b1));
}
__device__ __forceinline__ void cp16(uint32_t saddr, const void* g) {
    asm volatile("cp.async.cg.shared.global [%0], [%1], 16;" :: "r"(saddr), "l"(g));
}
#define CP_COMMIT() asm volatile("cp.async.commit_group;" ::: "memory")
#define CP_WAIT1()  asm volatile("cp.async.wait_group 1;" ::: "memory")
#define CP_WAIT0()  asm volatile("cp.async.wait_group 0;" ::: "memory")

__device__ __forceinline__ void split_pack(float a, float b, uint32_t& hi, uint32_t& lo) {
    __nv_bfloat162 h = __floats2bfloat162_rn(a, b);
    hi = *(uint32_t*)&h;
    __nv_bfloat162 l = __floats2bfloat162_rn(a - __bfloat162float(h.x),
                                             b - __bfloat162float(h.y));
    lo = *(uint32_t*)&l;
}
__device__ __forceinline__ void split4_store(float4 v, __nv_bfloat16* hp, __nv_bfloat16* lp) {
    uint32_t h0, l0, h1, l1;
    split_pack(v.x, v.y, h0, l0);
    split_pack(v.z, v.w, h1, l1);
    *(uint2*)hp = make_uint2(h0, h1);
    *(uint2*)lp = make_uint2(l0, l1);
}

// ---------------- LayerNorm ----------------
__global__ __launch_bounds__(256)
void layernorm_kernel(const float* __restrict__ x, const float* __restrict__ w,
                      const float* __restrict__ b) {
    int s = blockIdx.x, tid = threadIdx.x;
    const float* row = x + (size_t)s * HID;
    float4 a = *(const float4*)(row + tid * 4);
    float4 c = *(const float4*)(row + 1024 + tid * 4);
    float s1 = a.x + a.y + a.z + a.w + c.x + c.y + c.z + c.w;
    float s2 = a.x*a.x + a.y*a.y + a.z*a.z + a.w*a.w
             + c.x*c.x + c.y*c.y + c.z*c.z + c.w*c.w;
    #pragma unroll
    for (int off = 16; off; off >>= 1) {
        s1 += __shfl_xor_sync(0xffffffffu, s1, off);
        s2 += __shfl_xor_sync(0xffffffffu, s2, off);
    }
    __shared__ float r1[8], r2[8];
    int wrp = tid >> 5, lane = tid & 31;
    if (lane == 0) { r1[wrp] = s1; r2[wrp] = s2; }
    __syncthreads();
    if (tid == 0) {
        float t1 = 0.f, t2 = 0.f;
        #pragma unroll
        for (int i = 0; i < 8; i++) { t1 += r1[i]; t2 += r2[i]; }
        r1[0] = t1; r2[0] = t2;
    }
    __syncthreads();
    float mu = r1[0] * (1.f / HID);
    float var = r2[0] * (1.f / HID) - mu * mu;
    float rs = rsqrtf(var + EPS);
    size_t rbase = (size_t)s * HID;
    int c0 = tid * 4;
    float4 w0 = *(const float4*)(w + c0), b0 = *(const float4*)(b + c0);
    float4 o0 = make_float4((a.x-mu)*rs*w0.x+b0.x, (a.y-mu)*rs*w0.y+b0.y,
                            (a.z-mu)*rs*w0.z+b0.z, (a.w-mu)*rs*w0.w+b0.w);
    split4_store(o0, g_lnx_hi + rbase + c0, g_lnx_lo + rbase + c0);
    int c1 = 1024 + tid * 4;
    float4 w1 = *(const float4*)(w + c1), b1 = *(const float4*)(b + c1);
    float4 o1 = make_float4((c.x-mu)*rs*w1.x+b1.x, (c.y-mu)*rs*w1.y+b1.y,
                            (c.z-mu)*rs*w1.z+b1.z, (c.w-mu)*rs*w1.w+b1.w);
    split4_store(o1, g_lnx_hi + rbase + c1, g_lnx_lo + rbase + c1);
}

__global__ __launch_bounds__(256)
void splitw_kernel(const float* __restrict__ x, int which, int n) {
    __nv_bfloat16* hi = which ? g_wproj_hi : g_wqkv_hi;
    __nv_bfloat16* lo = which ? g_wproj_lo : g_wqkv_lo;
    int i = (blockIdx.x * 256 + threadIdx.x) * 4;
    if (i < n) split4_store(*(const float4*)(x + i), hi + i, lo + i);
}

// ---- QKV GEMM: 256 threads, 64x128 CTA tile, warp tile 32x32, 3 CTAs/SM ----
#define BK 32
#define QA_HI 0
#define QA_LO 4096
#define QB_HI 8192
#define QB_LO 16384
#define QSTAGE 24576
#define QSMEM (3 * QSTAGE)

__global__ __launch_bounds__(256, 3)
void gemm_qkv_kernel(const float* __restrict__ bias) {
    extern __shared__ __align__(1024) char smem[];
    const int NCHUNK = HID / BK;   // 64
    uint32_t sb = smem_u32(smem);
    int tid = threadIdx.x, wid = tid >> 5, lane = tid & 31;
    int row0 = blockIdx.y * 64, col0 = blockIdx.x * 128;
    int wm = wid >> 2, wn = wid & 3;

    int soffA; size_t gaA;
    {
        int r = tid >> 2, c16 = tid & 3, tr = r & 15;
        soffA = ((r >> 4) * 2 + (c16 >> 1)) * 512 + tr * 32
              + (((c16 & 1) ^ ((tr >> 2) & 1))) * 16;
        gaA = (size_t)(row0 + r) * HID + c16 * 8;
    }
    int soffB[2]; size_t gbB[2];
    #pragma unroll
    for (int j = 0; j < 2; j++) {
        int v = tid + j * 256;
        int r = v >> 2, c16 = v & 3, tr = r & 15;
        soffB[j] = ((r >> 4) * 2 + (c16 >> 1)) * 512 + tr * 32
                 + (((c16 & 1) ^ ((tr >> 2) & 1))) * 16;
        gbB[j] = (size_t)(col0 + r) * HID + c16 * 8;
    }
    float acc[2][4][4];
    #pragma unroll
    for (int i = 0; i < 2; i++)
        #pragma unroll
        for (int j = 0; j < 4; j++)
            #pragma unroll
            for (int q = 0; q < 4; q++) acc[i][j][q] = 0.f;
    int lr = lane & 15, lch = lane >> 4;
    int laneoff = lr * 32 + ((lch ^ ((lr >> 2) & 1))) * 16;

    #pragma unroll
    for (int c = 0; c < 2; c++) {
        uint32_t base = sb + c * QSTAGE;
        int k0 = c * BK;
        cp16(base + QA_HI + soffA, g_lnx_hi + gaA + k0);
        cp16(base + QA_LO + soffA, g_lnx_lo + gaA + k0);
        #pragma unroll
        for (int j = 0; j < 2; j++) {
            cp16(base + QB_HI + soffB[j], g_wqkv_hi + gbB[j] + k0);
            cp16(base + QB_LO + soffB[j], g_wqkv_lo + gbB[j] + k0);
        }
        CP_COMMIT();
    }

    int buf = 0, bpre = 2;
    for (int c = 0; c < NCHUNK; c++) {
        if (c == NCHUNK - 1) CP_WAIT0(); else CP_WAIT1();
        __syncthreads();
        if (c + 2 < NCHUNK) {
            uint32_t base = sb + bpre * QSTAGE;
            int k0 = (c + 2) * BK;
            cp16(base + QA_HI + soffA, g_lnx_hi + gaA + k0);
            cp16(base + QA_LO + soffA, g_lnx_lo + gaA + k0);
            #pragma unroll
            for (int j = 0; j < 2; j++) {
                cp16(base + QB_HI + soffB[j], g_wqkv_hi + gbB[j] + k0);
                cp16(base + QB_LO + soffB[j], g_wqkv_lo + gbB[j] + k0);
            }
            CP_COMMIT();
        }
        uint32_t stg = sb + buf * QSTAGE;
        #pragma unroll
        for (int kt = 0; kt < 2; kt++) {
            uint32_t aT0 = stg + ((wm * 2) * 2 + kt) * 512 + laneoff;
            uint32_t bT0 = stg + ((wn * 2) * 2 + kt) * 512 + laneoff;
            uint32_t bH[2][4], bL[2][4];
            #pragma unroll
            for (int j = 0; j < 2; j++) ldm_x4(bH[j], bT0 + QB_HI + j * 1024);
            #pragma unroll
            for (int j = 0; j < 2; j++) ldm_x4(bL[j], bT0 + QB_LO + j * 1024);
            #pragma unroll
            for (int mt = 0; mt < 2; mt++) {
                uint32_t aH[4], aL[4];
                ldm_x4(aH, aT0 + QA_HI + mt * 1024);
                #pragma unroll
                for (int j = 0; j < 2; j++) {
                    mma_bf16(acc[mt][j*2+0], aH, bH[j][0], bH[j][2]);
                    mma_bf16(acc[mt][j*2+1], aH, bH[j][1], bH[j][3]);
                }
                ldm_x4(aL, aT0 + QA_LO + mt * 1024);
                #pragma unroll
                for (int j = 0; j < 2; j++) {
                    mma_bf16(acc[mt][j*2+0], aH, bL[j][0], bL[j][2]);
                    mma_bf16(acc[mt][j*2+1], aH, bL[j][1], bL[j][3]);
                }
                #pragma unroll
                for (int j = 0; j < 2; j++) {
                    mma_bf16(acc[mt][j*2+0], aL, bH[j][0], bH[j][2]);
                    mma_bf16(acc[mt][j*2+1], aL, bH[j][1], bH[j][3]);
                }
            }
        }
        buf = (buf == 2) ? 0 : buf + 1;
        bpre = (bpre == 2) ? 0 : bpre + 1;
    }

    int rg = lane >> 2, cg = (lane & 3) * 2;
    #pragma unroll
    for (int mt = 0; mt < 2; mt++) {
        int row = row0 + wm * 32 + mt * 16 + rg;
        #pragma unroll
        for (int n8 = 0; n8 < 4; n8++) {
            int col = col0 + wn * 32 + n8 * 8 + cg;
            float b0 = bias[col], b1 = bias[col + 1];
            int seg = col >> 11, cs = col & 2047;
            float sc = (seg == 0) ? QSCALE : 1.f;
            __nv_bfloat16 *hp = (seg == 0) ? g_q_hi : (seg == 1) ? g_k_hi : g_v_hi;
            __nv_bfloat16 *lp = (seg == 0) ? g_q_lo : (seg == 1) ? g_k_lo : g_v_lo;
            uint32_t hi, lo;
            split_pack((acc[mt][n8][0]+b0)*sc, (acc[mt][n8][1]+b1)*sc, hi, lo);
            *(uint32_t*)(hp + (size_t)row * HID + cs) = hi;
            *(uint32_t*)(lp + (size_t)row * HID + cs) = lo;
            split_pack((acc[mt][n8][2]+b0)*sc, (acc[mt][n8][3]+b1)*sc, hi, lo);
            *(uint32_t*)(hp + (size_t)(row + 8) * HID + cs) = hi;
            *(uint32_t*)(lp + (size_t)(row + 8) * HID + cs) = lo;
        }
    }
}

// ---- Proj GEMM: 512 threads, 128x256 tile ----
#define A_HI_OFF 0
#define A_LO_OFF 8192
#define B_HI_OFF 16384
#define B_LO_OFF 32768
#define STAGE_BYTES 49152
#define GSMEM (3 * STAGE_BYTES)

__global__ __launch_bounds__(512, 1)
void gemm_proj_kernel(const float* __restrict__ bias, float* __restrict__ Cout) {
    extern __shared__ __align__(1024) char smem[];
    const int NCHUNK = HID / BK;
    uint32_t sb = smem_u32(smem);
    int tid = threadIdx.x, wid = tid >> 5, lane = tid & 31;
    int row0 = blockIdx.y * 128, col0 = blockIdx.x * 256;
    int wm = wid >> 3, wn = wid & 7;

    int soffA; size_t gaA;
    {
        int r = tid >> 2, c16 = tid & 3, tr = r & 15;
        soffA = ((r >> 4) * 2 + (c16 >> 1)) * 512 + tr * 32
              + (((c16 & 1) ^ ((tr >> 2) & 1))) * 16;
        gaA = (size_t)(row0 + r) * HID + c16 * 8;
    }
    int soffB[2]; size_t gbB[2];
    #pragma unroll
    for (int j = 0; j < 2; j++) {
        int v = tid + j * 512;
        int r = v >> 2, c16 = v & 3, tr = r & 15;
        soffB[j] = ((r >> 4) * 2 + (c16 >> 1)) * 512 + tr * 32
                 + (((c16 & 1) ^ ((tr >> 2) & 1))) * 16;
        gbB[j] = (size_t)(col0 + r) * HID + c16 * 8;
    }
    float acc[4][4][4];
    #pragma unroll
    for (int i = 0; i < 4; i++)
        #pragma unroll
        for (int j = 0; j < 4; j++)
            #pragma unroll
            for (int q = 0; q < 4; q++) acc[i][j][q] = 0.f;
    int lr = lane & 15, lch = lane >> 4;
    int laneoff = lr * 32 + ((lch ^ ((lr >> 2) & 1))) * 16;

    #pragma unroll
    for (int c = 0; c < 2; c++) {
        uint32_t base = sb + c * STAGE_BYTES;
        int k0 = c * BK;
        cp16(base + A_HI_OFF + soffA, g_ctx_hi + gaA + k0);
        cp16(base + A_LO_OFF + soffA, g_ctx_lo + gaA + k0);
        #pragma unroll
        for (int j = 0; j < 2; j++) {
            cp16(base + B_HI_OFF + soffB[j], g_wproj_hi + gbB[j] + k0);
            cp16(base + B_LO_OFF + soffB[j], g_wproj_lo + gbB[j] + k0);
        }
        CP_COMMIT();
    }
    int buf = 0, bpre = 2;
    for (int c = 0; c < NCHUNK; c++) {
        if (c == NCHUNK - 1) CP_WAIT0(); else CP_WAIT1();
        __syncthreads();
        if (c + 2 < NCHUNK) {
            uint32_t base = sb + bpre * STAGE_BYTES;
            int k0 = (c + 2) * BK;
            cp16(base + A_HI_OFF + soffA, g_ctx_hi + gaA + k0);
            cp16(base + A_LO_OFF + soffA, g_ctx_lo + gaA + k0);
            #pragma unroll
            for (int j = 0; j < 2; j++) {
                cp16(base + B_HI_OFF + soffB[j], g_wproj_hi + gbB[j] + k0);
                cp16(base + B_LO_OFF + soffB[j], g_wproj_lo + gbB[j] + k0);
            }
            CP_COMMIT();
        }
        uint32_t stg = sb + buf * STAGE_BYTES;
        #pragma unroll
        for (int kt = 0; kt < 2; kt++) {
            uint32_t aT0 = stg + ((wm * 4) * 2 + kt) * 512 + laneoff;
            uint32_t bT0 = stg + ((wn * 2) * 2 + kt) * 512 + laneoff;
            uint32_t bH[2][4], bL[2][4];
            #pragma unroll
            for (int j = 0; j < 2; j++) ldm_x4(bH[j], bT0 + B_HI_OFF + j * 1024);
            #pragma unroll
            for (int j = 0; j < 2; j++) ldm_x4(bL[j], bT0 + B_LO_OFF + j * 1024);
            #pragma unroll
            for (int mt = 0; mt < 4; mt++) {
                uint32_t aH[4], aL[4];
                ldm_x4(aH, aT0 + A_HI_OFF + mt * 1024);
                #pragma unroll
                for (int j = 0; j < 2; j++) {
                    mma_bf16(acc[mt][j*2+0], aH, bH[j][0], bH[j][2]);
                    mma_bf16(acc[mt][j*2+1], aH, bH[j][1], bH[j][3]);
                }
                ldm_x4(aL, aT0 + A_LO_OFF + mt * 1024);
                #pragma unroll
                for (int j = 0; j < 2; j++) {
                    mma_bf16(acc[mt][j*2+0], aH, bL[j][0], bL[j][2]);
                    mma_bf16(acc[mt][j*2+1], aH, bL[j][1], bL[j][3]);
                }
                #pragma unroll
                for (int j = 0; j < 2; j++) {
                    mma_bf16(acc[mt][j*2+0], aL, bH[j][0], bH[j][2]);
                    mma_bf16(acc[mt][j*2+1], aL, bH[j][1], bH[j][3]);
                }
            }
        }
        buf = (buf == 2) ? 0 : buf + 1;
        bpre = (bpre == 2) ? 0 : bpre + 1;
    }
    int rg = lane >> 2, cg = (lane & 3) * 2;
    #pragma unroll
    for (int mt = 0; mt < 4; mt++) {
        int row = row0 + wm * 64 + mt * 16 + rg;
        #pragma unroll
        for (int n8 = 0; n8 < 4; n8++) {
            int col = col0 + wn * 32 + n8 * 8 + cg;
            float b0 = bias[col], b1 = bias[col + 1];
            *(float2*)(Cout + (size_t)row * HID + col) =
                make_float2(acc[mt][n8][0]+b0, acc[mt][n8][1]+b1);
            *(float2*)(Cout + (size_t)(row + 8) * HID + col) =
                make_float2(acc[mt][n8][2]+b0, acc[mt][n8][3]+b1);
        }
    }
}

// ---------------- FA2 attention, mma.sync bf16x3 (unchanged) ----------------
#define QH_OFF 0
#define QL_OFF 32768
#define ST_OFF 65536
#define ST_STRIDE 65536
#define AKH 0
#define AKL 16384
#define AVH 32768
#define AVL 49152
#define ASMEM (ST_OFF + 2 * ST_STRIDE)

__global__ __launch_bounds__(256, 1)
void attn_mma_kernel() {
    extern __shared__ __align__(1024) char smem[];
    uint32_t sb = smem_u32(smem);
    int tid = threadIdx.x, wid = tid >> 5, lane = tid & 31, l15 = lane & 15;
    int h = blockIdx.y;
    int qb = (int)gridDim.x - 1 - (int)blockIdx.x;
    int q0 = qb * 128;
    int ntiles = qb * 2 + 2;
    size_t hoff = (size_t)h * HD;

    int qs[8]; size_t qg[8];
    #pragma unroll
    for (int j = 0; j < 8; j++) {
        int v = tid + j * 256;
        int r = v >> 4, c16 = v & 15, tc = c16 >> 1;
        qs[j] = ((r >> 4) * 8 + tc) * 512 + (((r & 15) ^ tc) * 32)
              + (((c16 & 1) ^ ((r >> 2) & 1)) * 16);
        qg[j] = (size_t)(q0 + r) * HID + hoff + c16 * 8;
    }
    int ks[4]; size_t kg[4];
    #pragma unroll
    for (int j = 0; j < 4; j++) {
        int v = tid + j * 256;
        int r = v >> 4, c16 = v & 15, tc = c16 >> 1;
        ks[j] = ((r >> 4) * 8 + tc) * 512 + (((r & 15) ^ tc) * 32)
              + (((c16 & 1) ^ ((r >> 2) & 1)) * 16);
        kg[j] = (size_t)r * HID + hoff + c16 * 8;
    }

    #pragma unroll
    for (int j = 0; j < 8; j++) {
        cp16(sb + QH_OFF + qs[j], g_q_hi + qg[j]);
        cp16(sb + QL_OFF + qs[j], g_q_lo + qg[j]);
    }
    CP_COMMIT();
    #pragma unroll
    for (int t = 0; t < 2; t++) {
        uint32_t stb = sb + ST_OFF + t * ST_STRIDE;
        size_t kvb = (size_t)(t * 64) * HID;
        #pragma unroll
        for (int j = 0; j < 4; j++) {
            cp16(stb + AKH + ks[j], g_k_hi + kvb + kg[j]);
            cp16(stb + AKL + ks[j], g_k_lo + kvb + kg[j]);
            cp16(stb + AVH + ks[j], g_v_hi + kvb + kg[j]);
            cp16(stb + AVL + ks[j], g_v_lo + kvb + kg[j]);
        }
        CP_COMMIT();
    }

    int slotoff = ((lane >> 4) ^ ((lane >> 2) & 1)) * 16;
    int gr = q0 + wid * 16 + (lane >> 2);
    int colb = 2 * (lane & 3);

    float o[16][4];
    #pragma unroll
    for (int i = 0; i < 16; i++)
        #pragma unroll
        for (int j = 0; j < 4; j++) o[i][j] = 0.f;
    float m0 = -INFINITY, m1 = -INFINITY, l0 = 0.f, l1 = 0.f;

    for (int t = 0; t < ntiles; t++) {
        if (t >= ntiles - 2) CP_WAIT0(); else CP_WAIT1();
        __syncthreads();
        uint32_t stb = sb + ST_OFF + (t & 1) * ST_STRIDE;
        int kt0 = t * 64;
        bool active = (q0 + wid * 16 + 15) >= kt0;

        if (active) {
            float s[8][4];
            #pragma unroll
            for (int i = 0; i < 8; i++)
                #pragma unroll
                for (int j = 0; j < 4; j++) s[i][j] = 0.f;

            #pragma unroll
            for (int kc = 0; kc < 8; kc++) {
                int tl = ((l15 ^ kc) * 32) + slotoff;
                uint32_t qh[4], ql[4], kh[4][4], kl[4][4];
                ldm_x4(qh, sb + QH_OFF + (wid * 8 + kc) * 512 + tl);
                ldm_x4(ql, sb + QL_OFF + (wid * 8 + kc) * 512 + tl);
                #pragma unroll
                for (int ng = 0; ng < 4; ng++) ldm_x4(kh[ng], stb + AKH + (ng * 8 + kc) * 512 + tl);
                #pragma unroll
                for (int ng = 0; ng < 4; ng++) ldm_x4(kl[ng], stb + AKL + (ng * 8 + kc) * 512 + tl);
                #pragma unroll
                for (int ng = 0; ng < 4; ng++) {
                    mma_bf16(s[2*ng],   qh, kh[ng][0], kh[ng][2]);
                    mma_bf16(s[2*ng+1], qh, kh[ng][1], kh[ng][3]);
                    mma_bf16(s[2*ng],   qh, kl[ng][0], kl[ng][2]);
                    mma_bf16(s[2*ng+1], qh, kl[ng][1], kl[ng][3]);
                    mma_bf16(s[2*ng],   ql, kh[ng][0], kh[ng][2]);
                    mma_bf16(s[2*ng+1], ql, kh[ng][1], kh[ng][3]);
                }
            }

            if (kt0 + 63 > gr) {
                #pragma unroll
                for (int t8 = 0; t8 < 8; t8++) {
                    int col = kt0 + t8 * 8 + colb;
                    if (col > gr)         s[t8][0] = -INFINITY;
                    if (col + 1 > gr)     s[t8][1] = -INFINITY;
                    if (col > gr + 8)     s[t8][2] = -INFINITY;
                    if (col + 1 > gr + 8) s[t8][3] = -INFINITY;
                }
            }

            float tm0 = m0, tm1 = m1;
            #pragma unroll
            for (int t8 = 0; t8 < 8; t8++) {
                tm0 = fmaxf(tm0, fmaxf(s[t8][0], s[t8][1]));
                tm1 = fmaxf(tm1, fmaxf(s[t8][2], s[t8][3]));
            }
            tm0 = fmaxf(tm0, __shfl_xor_sync(0xffffffffu, tm0, 1));
            tm0 = fmaxf(tm0, __shfl_xor_sync(0xffffffffu, tm0, 2));
            tm1 = fmaxf(tm1, __shfl_xor_sync(0xffffffffu, tm1, 1));
            tm1 = fmaxf(tm1, __shfl_xor_sync(0xffffffffu, tm1, 2));
            float c0 = __expf(m0 - tm0), c1 = __expf(m1 - tm1);
            m0 = tm0; m1 = tm1;
            float rs0 = 0.f, rs1 = 0.f;
            #pragma unroll
            for (int t8 = 0; t8 < 8; t8++) {
                s[t8][0] = __expf(s[t8][0] - m0); rs0 += s[t8][0];
                s[t8][1] = __expf(s[t8][1] - m0); rs0 += s[t8][1];
                s[t8][2] = __expf(s[t8][2] - m1); rs1 += s[t8][2];
                s[t8][3] = __expf(s[t8][3] - m1); rs1 += s[t8][3];
            }
            rs0 += __shfl_xor_sync(0xffffffffu, rs0, 1);
            rs0 += __shfl_xor_sync(0xffffffffu, rs0, 2);
            rs1 += __shfl_xor_sync(0xffffffffu, rs1, 1);
            rs1 += __shfl_xor_sync(0xffffffffu, rs1, 2);
            l0 = l0 * c0 + rs0;
            l1 = l1 * c1 + rs1;
            #pragma unroll
            for (int i = 0; i < 16; i++) {
                o[i][0] *= c0; o[i][1] *= c0; o[i][2] *= c1; o[i][3] *= c1;
            }

            #pragma unroll
            for (int kc2 = 0; kc2 < 4; kc2++) {
                uint32_t ph[4], pl[4];
                split_pack(s[2*kc2][0],   s[2*kc2][1],   ph[0], pl[0]);
                split_pack(s[2*kc2][2],   s[2*kc2][3],   ph[1], pl[1]);
                split_pack(s[2*kc2+1][0], s[2*kc2+1][1], ph[2], pl[2]);
                split_pack(s[2*kc2+1][2], s[2*kc2+1][3], ph[3], pl[3]);
                #pragma unroll
                for (int dd = 0; dd < 8; dd++) {
                    int tl = ((l15 ^ dd) * 32) + slotoff;
                    uint32_t vh[4], vl[4];
                    ldm_x4t(vh, stb + AVH + (kc2 * 8 + dd) * 512 + tl);
                    ldm_x4t(vl, stb + AVL + (kc2 * 8 + dd) * 512 + tl);
                    mma_bf16(o[dd*2],   ph, vh[0], vh[1]);
                    mma_bf16(o[dd*2+1], ph, vh[2], vh[3]);
                    mma_bf16(o[dd*2],   ph, vl[0], vl[1]);
                    mma_bf16(o[dd*2+1], ph, vl[2], vl[3]);
                    mma_bf16(o[dd*2],   pl, vh[0], vh[1]);
                    mma_bf16(o[dd*2+1], pl, vh[2], vh[3]);
                }
            }
        }
        __syncthreads();
        if (t + 2 < ntiles) {
            uint32_t stb2 = sb + ST_OFF + (t & 1) * ST_STRIDE;
            size_t kvb = (size_t)((t + 2) * 64) * HID;
            #pragma unroll
            for (int j = 0; j < 4; j++) {
                cp16(stb2 + AKH + ks[j], g_k_hi + kvb + kg[j]);
                cp16(stb2 + AKL + ks[j], g_k_lo + kvb + kg[j]);
                cp16(stb2 + AVH + ks[j], g_v_hi + kvb + kg[j]);
                cp16(stb2 + AVL + ks[j], g_v_lo + kvb + kg[j]);
            }
            CP_COMMIT();
        }
    }

    float inv0 = 1.f / l0, inv1 = 1.f / l1;
    size_t ob0 = (size_t)gr * HID + hoff + colb;
    size_t ob1 = (size_t)(gr + 8) * HID + hoff + colb;
    #pragma unroll
    for (int n8 = 0; n8 < 16; n8++) {
        uint32_t hi, lo;
        split_pack(o[n8][0] * inv0, o[n8][1] * inv0, hi, lo);
        *(uint32_t*)(g_ctx_hi + ob0 + n8 * 8) = hi;
        *(uint32_t*)(g_ctx_lo + ob0 + n8 * 8) = lo;
        split_pack(o[n8][2] * inv1, o[n8][3] * inv1, hi, lo);
        *(uint32_t*)(g_ctx_hi + ob1 + n8 * 8) = hi;
        *(uint32_t*)(g_ctx_lo + ob1 + n8 * 8) = lo;
    }
}

extern "C" void kernel_launch(void* const* d_in, const int* in_sizes, int n_in,
                              void* d_out, int out_size) {
    const float* hs   = (const float*)d_in[0];
    const float* lw   = (const float*)d_in[1];
    const float* lb   = (const float*)d_in[2];
    const float* qkvw = (const float*)d_in[3];
    const float* qkvb = (const float*)d_in[4];
    const float* pw   = (const float*)d_in[5];
    const float* pb   = (const float*)d_in[6];
    float* out = (float*)d_out;

    cudaFuncSetAttribute(gemm_qkv_kernel, cudaFuncAttributeMaxDynamicSharedMemorySize, QSMEM);
    cudaFuncSetAttribute(gemm_proj_kernel, cudaFuncAttributeMaxDynamicSharedMemorySize, GSMEM);
    cudaFuncSetAttribute(attn_mma_kernel, cudaFuncAttributeMaxDynamicSharedMemorySize, ASMEM);

    layernorm_kernel<<<S_LEN, 256>>>(hs, lw, lb);
    splitw_kernel<<<(QKV_N * HID / 4) / 256, 256>>>(qkvw, 0, QKV_N * HID);
    splitw_kernel<<<(HID * HID / 4) / 256, 256>>>(pw, 1, HID * HID);
    gemm_qkv_kernel<<<dim3(QKV_N / 128, S_LEN / 64), 256, QSMEM>>>(qkvb);
    attn_mma_kernel<<<dim3(S_LEN / 128, NH), 256, ASMEM>>>();
    gemm_proj_kernel<<<dim3(HID / 256, S_LEN / 128), 512, GSMEM>>>(pb, out);
}

// round 17
// speedup vs baseline: 1.0837x; 1.0673x over previous
#include <cuda_runtime.h>
#include <cuda_bf16.h>
#include <math.h>
#include <stdint.h>

#define S_LEN 2048
#define HID   2048
#define NH    16
#define HD    128
#define QKV_N 6144
#define EPS   1e-5f
#define QSCALE 0.08838834764831845f

__device__ float         g_lnx32 [S_LEN * HID];
__device__ float         g_wqkv32[QKV_N * HID];
__device__ __nv_bfloat16 g_wproj_hi[HID * HID];
__device__ __nv_bfloat16 g_wproj_lo[HID * HID];
__device__ __nv_bfloat16 g_q_hi[S_LEN * HID];
__device__ __nv_bfloat16 g_q_lo[S_LEN * HID];
__device__ __nv_bfloat16 g_k_hi[S_LEN * HID];
__device__ __nv_bfloat16 g_k_lo[S_LEN * HID];
__device__ __nv_bfloat16 g_v_hi[S_LEN * HID];
__device__ __nv_bfloat16 g_v_lo[S_LEN * HID];
__device__ __nv_bfloat16 g_ctx_hi[S_LEN * HID];
__device__ __nv_bfloat16 g_ctx_lo[S_LEN * HID];

__device__ __forceinline__ uint32_t smem_u32(const void* p) {
    uint32_t a;
    asm("{ .reg .u64 t; cvta.to.shared.u64 t, %1; cvt.u32.u64 %0, t; }" : "=r"(a) : "l"(p));
    return a;
}
__device__ __forceinline__ void ldm_x4(uint32_t* r, uint32_t addr) {
    asm volatile("ldmatrix.sync.aligned.m8n8.x4.shared.b16 {%0,%1,%2,%3}, [%4];"
        : "=r"(r[0]), "=r"(r[1]), "=r"(r[2]), "=r"(r[3]) : "r"(addr));
}
__device__ __forceinline__ void ldm_x4t(uint32_t* r, uint32_t addr) {
    asm volatile("ldmatrix.sync.aligned.m8n8.x4.trans.shared.b16 {%0,%1,%2,%3}, [%4];"
        : "=r"(r[0]), "=r"(r[1]), "=r"(r[2]), "=r"(r[3]) : "r"(addr));
}
__device__ __forceinline__ void mma_bf16(float* d, const uint32_t* a, uint32_t b0, uint32_t b1) {
    asm volatile("mma.sync.aligned.m16n8k16.row.col.f32.bf16.bf16.f32 "
        "{%0,%1,%2,%3}, {%4,%5,%6,%7}, {%8,%9}, {%0,%1,%2,%3};"
        : "+f"(d[0]), "+f"(d[1]), "+f"(d[2]), "+f"(d[3])
        : "r"(a[0]), "r"(a[1]), "r"(a[2]), "r"(a[3]), "r"(b0), "r"(b1));
}
__device__ __forceinline__ void mma_tf32(float* d, const uint32_t* a, uint32_t b0, uint32_t b1) {
    asm volatile("mma.sync.aligned.m16n8k8.row.col.f32.tf32.tf32.f32 "
        "{%0,%1,%2,%3}, {%4,%5,%6,%7}, {%8,%9}, {%0,%1,%2,%3};"
        : "+f"(d[0]), "+f"(d[1]), "+f"(d[2]), "+f"(d[3])
        : "r"(a[0]), "r"(a[1]), "r"(a[2]), "r"(a[3]), "r"(b0), "r"(b1));
}
__device__ __forceinline__ void cp16(uint32_t saddr, const void* g) {
    asm volatile("cp.async.cg.shared.global [%0], [%1], 16;" :: "r"(saddr), "l"(g));
}
#define CP_COMMIT() asm volatile("cp.async.commit_group;" ::: "memory")
#define CP_WAIT1()  asm volatile("cp.async.wait_group 1;" ::: "memory")
#define CP_WAIT0()  asm volatile("cp.async.wait_group 0;" ::: "memory")

__device__ __forceinline__ float tf32r(float x) {
    uint32_t r;
    asm("cvt.rna.tf32.f32 %0, %1;" : "=r"(r) : "f"(x));
    return __uint_as_float(r);
}
__device__ __forceinline__ void split_pack(float a, float b, uint32_t& hi, uint32_t& lo) {
    __nv_bfloat162 h = __floats2bfloat162_rn(a, b);
    hi = *(uint32_t*)&h;
    __nv_bfloat162 l = __floats2bfloat162_rn(a - __bfloat162float(h.x),
                                             b - __bfloat162float(h.y));
    lo = *(uint32_t*)&l;
}
__device__ __forceinline__ void split4_store(float4 v, __nv_bfloat16* hp, __nv_bfloat16* lp) {
    uint32_t h0, l0, h1, l1;
    split_pack(v.x, v.y, h0, l0);
    split_pack(v.z, v.w, h1, l1);
    *(uint2*)hp = make_uint2(h0, h1);
    *(uint2*)lp = make_uint2(l0, l1);
}

// ---------------- LayerNorm: writes tf32-rounded fp32 ----------------
__global__ __launch_bounds__(256)
void layernorm_kernel(const float* __restrict__ x, const float* __restrict__ w,
                      const float* __restrict__ b) {
    int s = blockIdx.x, tid = threadIdx.x;
    const float* row = x + (size_t)s * HID;
    float4 a = *(const float4*)(row + tid * 4);
    float4 c = *(const float4*)(row + 1024 + tid * 4);
    float s1 = a.x + a.y + a.z + a.w + c.x + c.y + c.z + c.w;
    float s2 = a.x*a.x + a.y*a.y + a.z*a.z + a.w*a.w
             + c.x*c.x + c.y*c.y + c.z*c.z + c.w*c.w;
    #pragma unroll
    for (int off = 16; off; off >>= 1) {
        s1 += __shfl_xor_sync(0xffffffffu, s1, off);
        s2 += __shfl_xor_sync(0xffffffffu, s2, off);
    }
    __shared__ float r1[8], r2[8];
    int wrp = tid >> 5, lane = tid & 31;
    if (lane == 0) { r1[wrp] = s1; r2[wrp] = s2; }
    __syncthreads();
    if (tid == 0) {
        float t1 = 0.f, t2 = 0.f;
        #pragma unroll
        for (int i = 0; i < 8; i++) { t1 += r1[i]; t2 += r2[i]; }
        r1[0] = t1; r2[0] = t2;
    }
    __syncthreads();
    float mu = r1[0] * (1.f / HID);
    float var = r2[0] * (1.f / HID) - mu * mu;
    float rs = rsqrtf(var + EPS);
    size_t rbase = (size_t)s * HID;
    int c0 = tid * 4;
    float4 w0 = *(const float4*)(w + c0), b0 = *(const float4*)(b + c0);
    float4 o0 = make_float4(tf32r((a.x-mu)*rs*w0.x+b0.x), tf32r((a.y-mu)*rs*w0.y+b0.y),
                            tf32r((a.z-mu)*rs*w0.z+b0.z), tf32r((a.w-mu)*rs*w0.w+b0.w));
    *(float4*)(g_lnx32 + rbase + c0) = o0;
    int c1 = 1024 + tid * 4;
    float4 w1 = *(const float4*)(w + c1), b1 = *(const float4*)(b + c1);
    float4 o1 = make_float4(tf32r((c.x-mu)*rs*w1.x+b1.x), tf32r((c.y-mu)*rs*w1.y+b1.y),
                            tf32r((c.z-mu)*rs*w1.z+b1.z), tf32r((c.w-mu)*rs*w1.w+b1.w));
    *(float4*)(g_lnx32 + rbase + c1) = o1;
}

__global__ __launch_bounds__(256)
void prep_kernel(const float* __restrict__ x, int which, int n) {
    int i = (blockIdx.x * 256 + threadIdx.x) * 4;
    if (i >= n) return;
    float4 v = *(const float4*)(x + i);
    if (which == 0) {
        float4 o = make_float4(tf32r(v.x), tf32r(v.y), tf32r(v.z), tf32r(v.w));
        *(float4*)(g_wqkv32 + i) = o;
    } else {
        split4_store(v, g_wproj_hi + i, g_wproj_lo + i);
    }
}

// ---- QKV GEMM: TF32 single-pass. 256 thr, 64x128 tile, warp tile 32x32 ----
#define BK 32
#define TROW 160
#define TA_OFF 0
#define TB_OFF 10240
#define TSTAGE 30720
#define TSMEM (3 * TSTAGE)

__global__ __launch_bounds__(256, 2)
void gemm_qkv_kernel(const float* __restrict__ bias) {
    extern __shared__ __align__(1024) char smem[];
    const int NCHUNK = HID / BK;   // 64
    uint32_t sb = smem_u32(smem);
    int tid = threadIdx.x, wid = tid >> 5, lane = tid & 31;
    int row0 = blockIdx.y * 64, col0 = blockIdx.x * 128;
    int wm = wid >> 2, wn = wid & 3;
    int l4 = lane >> 2, lc = lane & 3;

    int sA[2]; size_t gA[2];
    #pragma unroll
    for (int j = 0; j < 2; j++) {
        int v = tid + j * 256;
        int r = v >> 3, c4 = v & 7;
        sA[j] = r * TROW + c4 * 16;
        gA[j] = (size_t)(row0 + r) * HID + c4 * 4;
    }
    int sB[4]; size_t gB[4];
    #pragma unroll
    for (int j = 0; j < 4; j++) {
        int v = tid + j * 256;
        int r = v >> 3, c4 = v & 7;
        sB[j] = r * TROW + c4 * 16;
        gB[j] = (size_t)(col0 + r) * HID + c4 * 4;
    }

    float acc[2][4][4];
    #pragma unroll
    for (int i = 0; i < 2; i++)
        #pragma unroll
        for (int j = 0; j < 4; j++)
            #pragma unroll
            for (int q = 0; q < 4; q++) acc[i][j][q] = 0.f;

    #pragma unroll
    for (int c = 0; c < 2; c++) {
        uint32_t base = sb + c * TSTAGE;
        int k0 = c * BK;
        #pragma unroll
        for (int j = 0; j < 2; j++) cp16(base + TA_OFF + sA[j], g_lnx32 + gA[j] + k0);
        #pragma unroll
        for (int j = 0; j < 4; j++) cp16(base + TB_OFF + sB[j], g_wqkv32 + gB[j] + k0);
        CP_COMMIT();
    }

    int buf = 0, bpre = 2;
    for (int c = 0; c < NCHUNK; c++) {
        if (c == NCHUNK - 1) CP_WAIT0(); else CP_WAIT1();
        __syncthreads();
        if (c + 2 < NCHUNK) {
            uint32_t base = sb + bpre * TSTAGE;
            int k0 = (c + 2) * BK;
            #pragma unroll
            for (int j = 0; j < 2; j++) cp16(base + TA_OFF + sA[j], g_lnx32 + gA[j] + k0);
            #pragma unroll
            for (int j = 0; j < 4; j++) cp16(base + TB_OFF + sB[j], g_wqkv32 + gB[j] + k0);
            CP_COMMIT();
        }
        char* stg = smem + buf * TSTAGE;
        #pragma unroll
        for (int g = 0; g < 4; g++) {
            int kc = g * 8 + lc;
            uint32_t bf[4][2];
            #pragma unroll
            for (int j = 0; j < 4; j++) {
                const char* bp = stg + TB_OFF + (wn * 32 + j * 8 + l4) * TROW + kc * 4;
                bf[j][0] = *(const uint32_t*)bp;
                bf[j][1] = *(const uint32_t*)(bp + 16);
            }
            #pragma unroll
            for (int mt = 0; mt < 2; mt++) {
                const char* ap = stg + TA_OFF + (wm * 32 + mt * 16 + l4) * TROW + kc * 4;
                uint32_t af[4];
                af[0] = *(const uint32_t*)ap;
                af[1] = *(const uint32_t*)(ap + 8 * TROW);
                af[2] = *(const uint32_t*)(ap + 16);
                af[3] = *(const uint32_t*)(ap + 8 * TROW + 16);
                #pragma unroll
                for (int j = 0; j < 4; j++)
                    mma_tf32(acc[mt][j], af, bf[j][0], bf[j][1]);
            }
        }
        buf = (buf == 2) ? 0 : buf + 1;
        bpre = (bpre == 2) ? 0 : bpre + 1;
    }

    int rg = lane >> 2, cg = (lane & 3) * 2;
    #pragma unroll
    for (int mt = 0; mt < 2; mt++) {
        int row = row0 + wm * 32 + mt * 16 + rg;
        #pragma unroll
        for (int n8 = 0; n8 < 4; n8++) {
            int col = col0 + wn * 32 + n8 * 8 + cg;
            float b0 = bias[col], b1 = bias[col + 1];
            int seg = col >> 11, cs = col & 2047;
            float sc = (seg == 0) ? QSCALE : 1.f;
            __nv_bfloat16 *hp = (seg == 0) ? g_q_hi : (seg == 1) ? g_k_hi : g_v_hi;
            __nv_bfloat16 *lp = (seg == 0) ? g_q_lo : (seg == 1) ? g_k_lo : g_v_lo;
            uint32_t hi, lo;
            split_pack((acc[mt][n8][0]+b0)*sc, (acc[mt][n8][1]+b1)*sc, hi, lo);
            *(uint32_t*)(hp + (size_t)row * HID + cs) = hi;
            *(uint32_t*)(lp + (size_t)row * HID + cs) = lo;
            split_pack((acc[mt][n8][2]+b0)*sc, (acc[mt][n8][3]+b1)*sc, hi, lo);
            *(uint32_t*)(hp + (size_t)(row + 8) * HID + cs) = hi;
            *(uint32_t*)(lp + (size_t)(row + 8) * HID + cs) = lo;
        }
    }
}

// ---- Proj GEMM: bf16x3, 512 threads, 128x256 tile ----
#define A_HI_OFF 0
#define A_LO_OFF 8192
#define B_HI_OFF 16384
#define B_LO_OFF 32768
#define STAGE_BYTES 49152
#define GSMEM (3 * STAGE_BYTES)

__global__ __launch_bounds__(512, 1)
void gemm_proj_kernel(const float* __restrict__ bias, float* __restrict__ Cout) {
    extern __shared__ __align__(1024) char smem[];
    const int NCHUNK = HID / BK;
    uint32_t sb = smem_u32(smem);
    int tid = threadIdx.x, wid = tid >> 5, lane = tid & 31;
    int row0 = blockIdx.y * 128, col0 = blockIdx.x * 256;
    int wm = wid >> 3, wn = wid & 7;

    int soffA; size_t gaA;
    {
        int r = tid >> 2, c16 = tid & 3, tr = r & 15;
        soffA = ((r >> 4) * 2 + (c16 >> 1)) * 512 + tr * 32
              + (((c16 & 1) ^ ((tr >> 2) & 1))) * 16;
        gaA = (size_t)(row0 + r) * HID + c16 * 8;
    }
    int soffB[2]; size_t gbB[2];
    #pragma unroll
    for (int j = 0; j < 2; j++) {
        int v = tid + j * 512;
        int r = v >> 2, c16 = v & 3, tr = r & 15;
        soffB[j] = ((r >> 4) * 2 + (c16 >> 1)) * 512 + tr * 32
                 + (((c16 & 1) ^ ((tr >> 2) & 1))) * 16;
        gbB[j] = (size_t)(col0 + r) * HID + c16 * 8;
    }
    float acc[4][4][4];
    #pragma unroll
    for (int i = 0; i < 4; i++)
        #pragma unroll
        for (int j = 0; j < 4; j++)
            #pragma unroll
            for (int q = 0; q < 4; q++) acc[i][j][q] = 0.f;
    int lr = lane & 15, lch = lane >> 4;
    int laneoff = lr * 32 + ((lch ^ ((lr >> 2) & 1))) * 16;

    #pragma unroll
    for (int c = 0; c < 2; c++) {
        uint32_t base = sb + c * STAGE_BYTES;
        int k0 = c * BK;
        cp16(base + A_HI_OFF + soffA, g_ctx_hi + gaA + k0);
        cp16(base + A_LO_OFF + soffA, g_ctx_lo + gaA + k0);
        #pragma unroll
        for (int j = 0; j < 2; j++) {
            cp16(base + B_HI_OFF + soffB[j], g_wproj_hi + gbB[j] + k0);
            cp16(base + B_LO_OFF + soffB[j], g_wproj_lo + gbB[j] + k0);
        }
        CP_COMMIT();
    }
    int buf = 0, bpre = 2;
    for (int c = 0; c < NCHUNK; c++) {
        if (c == NCHUNK - 1) CP_WAIT0(); else CP_WAIT1();
        __syncthreads();
        if (c + 2 < NCHUNK) {
            uint32_t base = sb + bpre * STAGE_BYTES;
            int k0 = (c + 2) * BK;
            cp16(base + A_HI_OFF + soffA, g_ctx_hi + gaA + k0);
            cp16(base + A_LO_OFF + soffA, g_ctx_lo + gaA + k0);
            #pragma unroll
            for (int j = 0; j < 2; j++) {
                cp16(base + B_HI_OFF + soffB[j], g_wproj_hi + gbB[j] + k0);
                cp16(base + B_LO_OFF + soffB[j], g_wproj_lo + gbB[j] + k0);
            }
            CP_COMMIT();
        }
        uint32_t stg = sb + buf * STAGE_BYTES;
        #pragma unroll
        for (int kt = 0; kt < 2; kt++) {
            uint32_t aT0 = stg + ((wm * 4) * 2 + kt) * 512 + laneoff;
            uint32_t bT0 = stg + ((wn * 2) * 2 + kt) * 512 + laneoff;
            uint32_t bH[2][4], bL[2][4];
            #pragma unroll
            for (int j = 0; j < 2; j++) ldm_x4(bH[j], bT0 + B_HI_OFF + j * 1024);
            #pragma unroll
            for (int j = 0; j < 2; j++) ldm_x4(bL[j], bT0 + B_LO_OFF + j * 1024);
            #pragma unroll
            for (int mt = 0; mt < 4; mt++) {
                uint32_t aH[4], aL[4];
                ldm_x4(aH, aT0 + A_HI_OFF + mt * 1024);
                #pragma unroll
                for (int j = 0; j < 2; j++) {
                    mma_bf16(acc[mt][j*2+0], aH, bH[j][0], bH[j][2]);
                    mma_bf16(acc[mt][j*2+1], aH, bH[j][1], bH[j][3]);
                }
                ldm_x4(aL, aT0 + A_LO_OFF + mt * 1024);
                #pragma unroll
                for (int j = 0; j < 2; j++) {
                    mma_bf16(acc[mt][j*2+0], aH, bL[j][0], bL[j][2]);
                    mma_bf16(acc[mt][j*2+1], aH, bL[j][1], bL[j][3]);
                }
                #pragma unroll
                for (int j = 0; j < 2; j++) {
                    mma_bf16(acc[mt][j*2+0], aL, bH[j][0], bH[j][2]);
                    mma_bf16(acc[mt][j*2+1], aL, bH[j][1], bH[j][3]);
                }
            }
        }
        buf = (buf == 2) ? 0 : buf + 1;
        bpre = (bpre == 2) ? 0 : bpre + 1;
    }
    int rg = lane >> 2, cg = (lane & 3) * 2;
    #pragma unroll
    for (int mt = 0; mt < 4; mt++) {
        int row = row0 + wm * 64 + mt * 16 + rg;
        #pragma unroll
        for (int n8 = 0; n8 < 4; n8++) {
            int col = col0 + wn * 32 + n8 * 8 + cg;
            float b0 = bias[col], b1 = bias[col + 1];
            *(float2*)(Cout + (size_t)row * HID + col) =
                make_float2(acc[mt][n8][0]+b0, acc[mt][n8][1]+b1);
            *(float2*)(Cout + (size_t)(row + 8) * HID + col) =
                make_float2(acc[mt][n8][2]+b0, acc[mt][n8][3]+b1);
        }
    }
}

// ---------------- FA2 attention, mma.sync bf16x3 (unchanged) ----------------
#define QH_OFF 0
#define QL_OFF 32768
#define ST_OFF 65536
#define ST_STRIDE 65536
#define AKH 0
#define AKL 16384
#define AVH 32768
#define AVL 49152
#define ASMEM (ST_OFF + 2 * ST_STRIDE)

__global__ __launch_bounds__(256, 1)
void attn_mma_kernel() {
    extern __shared__ __align__(1024) char smem[];
    uint32_t sb = smem_u32(smem);
    int tid = threadIdx.x, wid = tid >> 5, lane = tid & 31, l15 = lane & 15;
    int h = blockIdx.y;
    int qb = (int)gridDim.x - 1 - (int)blockIdx.x;
    int q0 = qb * 128;
    int ntiles = qb * 2 + 2;
    size_t hoff = (size_t)h * HD;

    int qs[8]; size_t qg[8];
    #pragma unroll
    for (int j = 0; j < 8; j++) {
        int v = tid + j * 256;
        int r = v >> 4, c16 = v & 15, tc = c16 >> 1;
        qs[j] = ((r >> 4) * 8 + tc) * 512 + (((r & 15) ^ tc) * 32)
              + (((c16 & 1) ^ ((r >> 2) & 1)) * 16);
        qg[j] = (size_t)(q0 + r) * HID + hoff + c16 * 8;
    }
    int ks[4]; size_t kg[4];
    #pragma unroll
    for (int j = 0; j < 4; j++) {
        int v = tid + j * 256;
        int r = v >> 4, c16 = v & 15, tc = c16 >> 1;
        ks[j] = ((r >> 4) * 8 + tc) * 512 + (((r & 15) ^ tc) * 32)
              + (((c16 & 1) ^ ((r >> 2) & 1)) * 16);
        kg[j] = (size_t)r * HID + hoff + c16 * 8;
    }

    #pragma unroll
    for (int j = 0; j < 8; j++) {
        cp16(sb + QH_OFF + qs[j], g_q_hi + qg[j]);
        cp16(sb + QL_OFF + qs[j], g_q_lo + qg[j]);
    }
    CP_COMMIT();
    #pragma unroll
    for (int t = 0; t < 2; t++) {
        uint32_t stb = sb + ST_OFF + t * ST_STRIDE;
        size_t kvb = (size_t)(t * 64) * HID;
        #pragma unroll
        for (int j = 0; j < 4; j++) {
            cp16(stb + AKH + ks[j], g_k_hi + kvb + kg[j]);
            cp16(stb + AKL + ks[j], g_k_lo + kvb + kg[j]);
            cp16(stb + AVH + ks[j], g_v_hi + kvb + kg[j]);
            cp16(stb + AVL + ks[j], g_v_lo + kvb + kg[j]);
        }
        CP_COMMIT();
    }

    int slotoff = ((lane >> 4) ^ ((lane >> 2) & 1)) * 16;
    int gr = q0 + wid * 16 + (lane >> 2);
    int colb = 2 * (lane & 3);

    float o[16][4];
    #pragma unroll
    for (int i = 0; i < 16; i++)
        #pragma unroll
        for (int j = 0; j < 4; j++) o[i][j] = 0.f;
    float m0 = -INFINITY, m1 = -INFINITY, l0 = 0.f, l1 = 0.f;

    for (int t = 0; t < ntiles; t++) {
        if (t >= ntiles - 2) CP_WAIT0(); else CP_WAIT1();
        __syncthreads();
        uint32_t stb = sb + ST_OFF + (t & 1) * ST_STRIDE;
        int kt0 = t * 64;
        bool active = (q0 + wid * 16 + 15) >= kt0;

        if (active) {
            float s[8][4];
            #pragma unroll
            for (int i = 0; i < 8; i++)
                #pragma unroll
                for (int j = 0; j < 4; j++) s[i][j] = 0.f;

            #pragma unroll
            for (int kc = 0; kc < 8; kc++) {
                int tl = ((l15 ^ kc) * 32) + slotoff;
                uint32_t qh[4], ql[4], kh[4][4], kl[4][4];
                ldm_x4(qh, sb + QH_OFF + (wid * 8 + kc) * 512 + tl);
                ldm_x4(ql, sb + QL_OFF + (wid * 8 + kc) * 512 + tl);
                #pragma unroll
                for (int ng = 0; ng < 4; ng++) ldm_x4(kh[ng], stb + AKH + (ng * 8 + kc) * 512 + tl);
                #pragma unroll
                for (int ng = 0; ng < 4; ng++) ldm_x4(kl[ng], stb + AKL + (ng * 8 + kc) * 512 + tl);
                #pragma unroll
                for (int ng = 0; ng < 4; ng++) {
                    mma_bf16(s[2*ng],   qh, kh[ng][0], kh[ng][2]);
                    mma_bf16(s[2*ng+1], qh, kh[ng][1], kh[ng][3]);
                    mma_bf16(s[2*ng],   qh, kl[ng][0], kl[ng][2]);
                    mma_bf16(s[2*ng+1], qh, kl[ng][1], kl[ng][3]);
                    mma_bf16(s[2*ng],   ql, kh[ng][0], kh[ng][2]);
                    mma_bf16(s[2*ng+1], ql, kh[ng][1], kh[ng][3]);
                }
            }

            if (kt0 + 63 > gr) {
                #pragma unroll
                for (int t8 = 0; t8 < 8; t8++) {
                    int col = kt0 + t8 * 8 + colb;
                    if (col > gr)         s[t8][0] = -INFINITY;
                    if (col + 1 > gr)     s[t8][1] = -INFINITY;
                    if (col > gr + 8)     s[t8][2] = -INFINITY;
                    if (col + 1 > gr + 8) s[t8][3] = -INFINITY;
                }
            }

            float tm0 = m0, tm1 = m1;
            #pragma unroll
            for (int t8 = 0; t8 < 8; t8++) {
                tm0 = fmaxf(tm0, fmaxf(s[t8][0], s[t8][1]));
                tm1 = fmaxf(tm1, fmaxf(s[t8][2], s[t8][3]));
            }
            tm0 = fmaxf(tm0, __shfl_xor_sync(0xffffffffu, tm0, 1));
            tm0 = fmaxf(tm0, __shfl_xor_sync(0xffffffffu, tm0, 2));
            tm1 = fmaxf(tm1, __shfl_xor_sync(0xffffffffu, tm1, 1));
            tm1 = fmaxf(tm1, __shfl_xor_sync(0xffffffffu, tm1, 2));
            float c0 = __expf(m0 - tm0), c1 = __expf(m1 - tm1);
            m0 = tm0; m1 = tm1;
            float rs0 = 0.f, rs1 = 0.f;
            #pragma unroll
            for (int t8 = 0; t8 < 8; t8++) {
                s[t8][0] = __expf(s[t8][0] - m0); rs0 += s[t8][0];
                s[t8][1] = __expf(s[t8][1] - m0); rs0 += s[t8][1];
                s[t8][2] = __expf(s[t8][2] - m1); rs1 += s[t8][2];
                s[t8][3] = __expf(s[t8][3] - m1); rs1 += s[t8][3];
            }
            rs0 += __shfl_xor_sync(0xffffffffu, rs0, 1);
            rs0 += __shfl_xor_sync(0xffffffffu, rs0, 2);
            rs1 += __shfl_xor_sync(0xffffffffu, rs1, 1);
            rs1 += __shfl_xor_sync(0xffffffffu, rs1, 2);
            l0 = l0 * c0 + rs0;
            l1 = l1 * c1 + rs1;
            #pragma unroll
            for (int i = 0; i < 16; i++) {
                o[i][0] *= c0; o[i][1] *= c0; o[i][2] *= c1; o[i][3] *= c1;
            }

            #pragma unroll
            for (int kc2 = 0; kc2 < 4; kc2++) {
                uint32_t ph[4], pl[4];
                split_pack(s[2*kc2][0],   s[2*kc2][1],   ph[0], pl[0]);
                split_pack(s[2*kc2][2],   s[2*kc2][3],   ph[1], pl[1]);
                split_pack(s[2*kc2+1][0], s[2*kc2+1][1], ph[2], pl[2]);
                split_pack(s[2*kc2+1][2], s[2*kc2+1][3], ph[3], pl[3]);
                #pragma unroll
                for (int dd = 0; dd < 8; dd++) {
                    int tl = ((l15 ^ dd) * 32) + slotoff;
                    uint32_t vh[4], vl[4];
                    ldm_x4t(vh, stb + AVH + (kc2 * 8 + dd) * 512 + tl);
                    ldm_x4t(vl, stb + AVL + (kc2 * 8 + dd) * 512 + tl);
                    mma_bf16(o[dd*2],   ph, vh[0], vh[1]);
                    mma_bf16(o[dd*2+1], ph, vh[2], vh[3]);
                    mma_bf16(o[dd*2],   ph, vl[0], vl[1]);
                    mma_bf16(o[dd*2+1], ph, vl[2], vl[3]);
                    mma_bf16(o[dd*2],   pl, vh[0], vh[1]);
                    mma_bf16(o[dd*2+1], pl, vh[2], vh[3]);
                }
            }
        }
        __syncthreads();
        if (t + 2 < ntiles) {
            uint32_t stb2 = sb + ST_OFF + (t & 1) * ST_STRIDE;
            size_t kvb = (size_t)((t + 2) * 64) * HID;
            #pragma unroll
            for (int j = 0; j < 4; j++) {
                cp16(stb2 + AKH + ks[j], g_k_hi + kvb + kg[j]);
                cp16(stb2 + AKL + ks[j], g_k_lo + kvb + kg[j]);
                cp16(stb2 + AVH + ks[j], g_v_hi + kvb + kg[j]);
                cp16(stb2 + AVL + ks[j], g_v_lo + kvb + kg[j]);
            }
            CP_COMMIT();
        }
    }

    float inv0 = 1.f / l0, inv1 = 1.f / l1;
    size_t ob0 = (size_t)gr * HID + hoff + colb;
    size_t ob1 = (size_t)(gr + 8) * HID + hoff + colb;
    #pragma unroll
    for (int n8 = 0; n8 < 16; n8++) {
        uint32_t hi, lo;
        split_pack(o[n8][0] * inv0, o[n8][1] * inv0, hi, lo);
        *(uint32_t*)(g_ctx_hi + ob0 + n8 * 8) = hi;
        *(uint32_t*)(g_ctx_lo + ob0 + n8 * 8) = lo;
        split_pack(o[n8][2] * inv1, o[n8][3] * inv1, hi, lo);
        *(uint32_t*)(g_ctx_hi + ob1 + n8 * 8) = hi;
        *(uint32_t*)(g_ctx_lo + ob1 + n8 * 8) = lo;
    }
}

extern "C" void kernel_launch(void* const* d_in, const int* in_sizes, int n_in,
                              void* d_out, int out_size) {
    const float* hs   = (const float*)d_in[0];
    const float* lw   = (const float*)d_in[1];
    const float* lb   = (const float*)d_in[2];
    const float* qkvw = (const float*)d_in[3];
    const float* qkvb = (const float*)d_in[4];
    const float* pw   = (const float*)d_in[5];
    const float* pb   = (const float*)d_in[6];
    float* out = (float*)d_out;

    cudaFuncSetAttribute(gemm_qkv_kernel, cudaFuncAttributeMaxDynamicSharedMemorySize, TSMEM);
    cudaFuncSetAttribute(gemm_proj_kernel, cudaFuncAttributeMaxDynamicSharedMemorySize, GSMEM);
    cudaFuncSetAttribute(attn_mma_kernel, cudaFuncAttributeMaxDynamicSharedMemorySize, ASMEM);

    layernorm_kernel<<<S_LEN, 256>>>(hs, lw, lb);
    prep_kernel<<<(QKV_N * HID / 4) / 256, 256>>>(qkvw, 0, QKV_N * HID);
    prep_kernel<<<(HID * HID / 4) / 256, 256>>>(pw, 1, HID * HID);
    gemm_qkv_kernel<<<dim3(QKV_N / 128, S_LEN / 64), 256, TSMEM>>>(qkvb);
    attn_mma_kernel<<<dim3(S_LEN / 128, NH), 256, ASMEM>>>();
    gemm_proj_kernel<<<dim3(HID / 256, S_LEN / 128), 512, GSMEM>>>(pb, out);
}